// round 6
// baseline (speedup 1.0000x reference)
#include <cuda_runtime.h>
#include <cuda_bf16.h>
#include <stdint.h>
#include <math.h>

#define NODES 50000
#define EDGES 600000
#define DIN 128
#define DHID 256

// ---------------- device scratch (static, no allocation) ----------------
__device__ int   g_cnt[NODES];
__device__ int   g_off[NODES];
__device__ int   g_cur[NODES];
__device__ int   g_csrc[EDGES];
__device__ __align__(16) float g_agg1[NODES * DIN];
__device__ float2 g_t12[NODES];
__device__ float2 g_w12[NODES];
__device__ float4 g_P[DHID];
__device__ float  g_c[2];
__device__ float2 g_s[NODES];
// precomputed bf16 hi/lo weight split, transposed to [n][k]
__device__ __align__(16) __nv_bfloat16 g_wbh[DHID * DHID];
__device__ __align__(16) __nv_bfloat16 g_wbl[DHID * DHID];

// ---------------- zero the histogram ----------------
__global__ void k_zero() {
    int i = blockIdx.x * blockDim.x + threadIdx.x;
    if (i < NODES) g_cnt[i] = 0;
}

// ---------------- histogram of dst ----------------
__global__ void k_hist(const int* __restrict__ dst, int E) {
    int e = blockIdx.x * blockDim.x + threadIdx.x;
    if (e < E) atomicAdd(&g_cnt[dst[e]], 1);
}

// ---------------- single-block exclusive scan over 50K counts ----------------
__global__ void __launch_bounds__(1024) k_scan() {
    __shared__ int part[1024];
    const int t = threadIdx.x;
    const int per = (NODES + 1023) / 1024;
    const int base = t * per;

    int sum = 0;
    for (int i = 0; i < per; i++) {
        int n = base + i;
        if (n < NODES) sum += g_cnt[n];
    }
    part[t] = sum;
    __syncthreads();
    for (int off = 1; off < 1024; off <<= 1) {
        int u = (t >= off) ? part[t - off] : 0;
        __syncthreads();
        part[t] += u;
        __syncthreads();
    }
    int run = part[t] - sum;
    for (int i = 0; i < per; i++) {
        int n = base + i;
        if (n < NODES) {
            g_off[n] = run;
            g_cur[n] = run;
            run += g_cnt[n];
        }
    }
}

// ---------------- CSR fill ----------------
__global__ void k_fill(const int* __restrict__ src,
                       const int* __restrict__ dst, int E) {
    int e = blockIdx.x * blockDim.x + threadIdx.x;
    if (e >= E) return;
    int d = dst[e];
    int pos = atomicAdd(&g_cur[d], 1);
    g_csrc[pos] = src[e];
}

// ---------------- layer-1 mean aggregate: warp per node, MLP=4 ----------
__global__ void __launch_bounds__(256) k_agg1(const float* __restrict__ x) {
    int n = blockIdx.x * 8 + (threadIdx.x >> 5);
    if (n >= NODES) return;
    int lane = threadIdx.x & 31;
    int start = g_off[n], cnt = g_cnt[n];

    float4 acc = make_float4(0.f, 0.f, 0.f, 0.f);
    int j = 0;
    for (; j + 4 <= cnt; j += 4) {
        int s0 = g_csrc[start + j];
        int s1 = g_csrc[start + j + 1];
        int s2 = g_csrc[start + j + 2];
        int s3 = g_csrc[start + j + 3];
        float4 v0 = ((const float4*)(x + (size_t)s0 * DIN))[lane];
        float4 v1 = ((const float4*)(x + (size_t)s1 * DIN))[lane];
        float4 v2 = ((const float4*)(x + (size_t)s2 * DIN))[lane];
        float4 v3 = ((const float4*)(x + (size_t)s3 * DIN))[lane];
        acc.x += (v0.x + v1.x) + (v2.x + v3.x);
        acc.y += (v0.y + v1.y) + (v2.y + v3.y);
        acc.z += (v0.z + v1.z) + (v2.z + v3.z);
        acc.w += (v0.w + v1.w) + (v2.w + v3.w);
    }
    for (; j < cnt; j++) {
        int s0 = g_csrc[start + j];
        float4 v0 = ((const float4*)(x + (size_t)s0 * DIN))[lane];
        acc.x += v0.x; acc.y += v0.y; acc.z += v0.z; acc.w += v0.w;
    }
    float r = 1.0f / fmaxf((float)cnt, 1.0f);
    acc.x *= r; acc.y *= r; acc.z *= r; acc.w *= r;
    ((float4*)(g_agg1 + (size_t)n * DIN))[lane] = acc;
}

// -------- fold layer 2 + link head into 4 projection vectors --------
__global__ void k_prep(const float* __restrict__ W2l, const float* __restrict__ W2r,
                       const float* __restrict__ Wlin, const float* __restrict__ b2l)
{
    int j = threadIdx.x;
    float u1 = 0.f, u2 = 0.f, v1 = 0.f, v2 = 0.f;
    for (int k = 0; k < DIN; k++) {
        float wa = Wlin[k], wb = Wlin[DIN + k];
        float l = W2l[j * DIN + k], r = W2r[j * DIN + k];
        u1 = fmaf(l, wa, u1); u2 = fmaf(l, wb, u2);
        v1 = fmaf(r, wa, v1); v2 = fmaf(r, wb, v2);
    }
    g_P[j] = make_float4(u1, u2, v1, v2);
    if (j == 0) {
        float c1 = 0.f, c2 = 0.f;
        for (int k = 0; k < DIN; k++) {
            c1 = fmaf(b2l[k], Wlin[k], c1);
            c2 = fmaf(b2l[k], Wlin[DIN + k], c2);
        }
        g_c[0] = c1; g_c[1] = c2;
    }
}

// -------- precompute weight hi/lo bf16 split, transposed to [n][k] --------
__global__ void k_prepw(const float* __restrict__ W1l, const float* __restrict__ W1r) {
    int idx = blockIdx.x * blockDim.x + threadIdx.x;   // 65536 threads
    int n = idx >> 8, k = idx & 255;
    float wv = (k < 128) ? W1l[(size_t)k * 256 + n]
                         : W1r[(size_t)(k - 128) * 256 + n];
    __nv_bfloat16 h = __float2bfloat16(wv);
    g_wbh[n * 256 + k] = h;
    g_wbl[n * 256 + k] = __float2bfloat16(wv - __bfloat162float(h));
}

// ====================== tensor-core layer-1 GEMM =========================
// D[64,256] = [agg1|x](64x256) @ [W1l;W1r](256x256), bf16 2-term split
// (3 mma passes: hi*hi + hi*lo + lo*hi), fp32 accum. Fused epilogue.
#define SA_STRIDE 264                 // 256 + 8 pad
#define SB_STRIDE 40                  // 32 + 8 pad

#define MMA_BF16(d, a, b0_, b1_)                                             \
    asm volatile("mma.sync.aligned.m16n8k16.row.col.f32.bf16.bf16.f32 "     \
        "{%0,%1,%2,%3}, {%4,%5,%6,%7}, {%8,%9}, {%0,%1,%2,%3};"             \
        : "+f"(d[0]), "+f"(d[1]), "+f"(d[2]), "+f"(d[3])                    \
        : "r"(a[0]), "r"(a[1]), "r"(a[2]), "r"(a[3]), "r"(b0_), "r"(b1_))

__global__ void __launch_bounds__(256, 2) k_l1(
    const float* __restrict__ x,
    const float* __restrict__ b1l)
{
    extern __shared__ char smraw[];
    __nv_bfloat16* sah = (__nv_bfloat16*)smraw;          // 64 x SA_STRIDE
    __nv_bfloat16* sal = sah + 64 * SA_STRIDE;
    __nv_bfloat16* sbh = sal + 64 * SA_STRIDE;           // 256 x SB_STRIDE ([n][k])
    __nv_bfloat16* sbl = sbh + 256 * SB_STRIDE;
    float4* spart = (float4*)(sbl + 256 * SB_STRIDE);    // [4][64]

    const int tid = threadIdx.x;
    const int node0 = blockIdx.x * 64;

    // ---- stage A (hi/lo split): cols 0..127 = agg1, 128..255 = x ----
    for (int i = tid; i < 64 * 64; i += 256) {
        int n = i >> 6, q = i & 63;
        int gn = node0 + n;
        float4 v = make_float4(0.f, 0.f, 0.f, 0.f);
        if (gn < NODES) {
            v = (q < 32) ? ((const float4*)(g_agg1 + (size_t)gn * DIN))[q]
                         : ((const float4*)(x      + (size_t)gn * DIN))[q - 32];
        }
        int base = n * SA_STRIDE + q * 4;
        float f[4] = {v.x, v.y, v.z, v.w};
#pragma unroll
        for (int j = 0; j < 4; j++) {
            __nv_bfloat16 h = __float2bfloat16(f[j]);
            sah[base + j] = h;
            sal[base + j] = __float2bfloat16(f[j] - __bfloat162float(h));
        }
    }

    const int w = tid >> 5, lane = tid & 31;
    const int wm = w >> 2, wn = w & 3;          // 2 m-warps x 4 n-warps
    const int r = lane >> 2, c = lane & 3;

    float acc[2][8][4];
#pragma unroll
    for (int a = 0; a < 2; a++)
#pragma unroll
        for (int b = 0; b < 8; b++)
#pragma unroll
            for (int d = 0; d < 4; d++) acc[a][b][d] = 0.f;

    for (int kc = 0; kc < 256; kc += 32) {
        __syncthreads();
        // ---- stage B chunk: pure uint2 copies from precomputed split ----
        for (int i = tid; i < 2048; i += 256) {
            int n = i >> 3, j = i & 7;            // row n, 4-elem group j
            *(uint2*)(sbh + n * SB_STRIDE + j * 4) =
                *(const uint2*)(g_wbh + n * 256 + kc + j * 4);
            *(uint2*)(sbl + n * SB_STRIDE + j * 4) =
                *(const uint2*)(g_wbl + n * 256 + kc + j * 4);
        }
        __syncthreads();

#pragma unroll
        for (int ks = 0; ks < 32; ks += 16) {
            const int k0 = kc + ks;
            uint32_t ah[2][4], al[2][4];
#pragma unroll
            for (int mt = 0; mt < 2; mt++) {
                int e = (wm * 32 + mt * 16 + r) * SA_STRIDE + k0 + 2 * c;
                ah[mt][0] = *(const uint32_t*)(sah + e);
                ah[mt][1] = *(const uint32_t*)(sah + e + 8 * SA_STRIDE);
                ah[mt][2] = *(const uint32_t*)(sah + e + 8);
                ah[mt][3] = *(const uint32_t*)(sah + e + 8 * SA_STRIDE + 8);
                al[mt][0] = *(const uint32_t*)(sal + e);
                al[mt][1] = *(const uint32_t*)(sal + e + 8 * SA_STRIDE);
                al[mt][2] = *(const uint32_t*)(sal + e + 8);
                al[mt][3] = *(const uint32_t*)(sal + e + 8 * SA_STRIDE + 8);
            }
#pragma unroll
            for (int nt = 0; nt < 8; nt++) {
                int e = (wn * 64 + nt * 8 + r) * SB_STRIDE + ks + 2 * c;
                uint32_t bh0 = *(const uint32_t*)(sbh + e);
                uint32_t bh1 = *(const uint32_t*)(sbh + e + 8);
                uint32_t bl0 = *(const uint32_t*)(sbl + e);
                uint32_t bl1 = *(const uint32_t*)(sbl + e + 8);
#pragma unroll
                for (int mt = 0; mt < 2; mt++) {
                    MMA_BF16(acc[mt][nt], ah[mt], bh0, bh1);
                    MMA_BF16(acc[mt][nt], ah[mt], bl0, bl1);
                    MMA_BF16(acc[mt][nt], al[mt], bh0, bh1);
                }
            }
        }
    }

    // ---- epilogue: bias + relu + project onto (u1,u2,v1,v2) ----
#pragma unroll
    for (int mt = 0; mt < 2; mt++) {
#pragma unroll
        for (int hh = 0; hh < 2; hh++) {
            float t1 = 0.f, t2 = 0.f, w1 = 0.f, w2 = 0.f;
#pragma unroll
            for (int nt = 0; nt < 8; nt++) {
                int col = wn * 64 + nt * 8 + 2 * c;
                float2 bb = *(const float2*)(b1l + col);
                float e0 = fmaxf(acc[mt][nt][2 * hh + 0] + bb.x, 0.f);
                float e1 = fmaxf(acc[mt][nt][2 * hh + 1] + bb.y, 0.f);
                float4 p0 = g_P[col], p1 = g_P[col + 1];
                t1 += e0 * p0.x + e1 * p1.x;
                t2 += e0 * p0.y + e1 * p1.y;
                w1 += e0 * p0.z + e1 * p1.z;
                w2 += e0 * p0.w + e1 * p1.w;
            }
#pragma unroll
            for (int off = 1; off <= 2; off <<= 1) {
                t1 += __shfl_xor_sync(0xffffffffu, t1, off);
                t2 += __shfl_xor_sync(0xffffffffu, t2, off);
                w1 += __shfl_xor_sync(0xffffffffu, w1, off);
                w2 += __shfl_xor_sync(0xffffffffu, w2, off);
            }
            if (c == 0) {
                int rl = wm * 32 + mt * 16 + hh * 8 + r;
                spart[wn * 64 + rl] = make_float4(t1, t2, w1, w2);
            }
        }
    }
    __syncthreads();
    if (tid < 64) {
        int gn = node0 + tid;
        if (gn < NODES) {
            float4 s0 = spart[tid],       s1 = spart[64 + tid];
            float4 s2 = spart[128 + tid], s3 = spart[192 + tid];
            g_t12[gn] = make_float2(s0.x + s1.x + s2.x + s3.x,
                                    s0.y + s1.y + s2.y + s3.y);
            g_w12[gn] = make_float2(s0.z + s1.z + s2.z + s3.z,
                                    s0.w + s1.w + s2.w + s3.w);
        }
    }
}

// -------- layer-2 aggregate (gather) + finalize, 4 lanes per node ------
__global__ void k_fin() {
    int g = blockIdx.x * blockDim.x + threadIdx.x;
    int n = g >> 2, l = g & 3;
    if (n >= NODES) return;
    int start = g_off[n], cnt = g_cnt[n];
    float a1 = 0.f, a2 = 0.f;
    for (int j = l; j < cnt; j += 4) {
        float2 t = g_t12[g_csrc[start + j]];
        a1 += t.x; a2 += t.y;
    }
#pragma unroll
    for (int off = 1; off <= 2; off <<= 1) {
        a1 += __shfl_xor_sync(0xffffffffu, a1, off);
        a2 += __shfl_xor_sync(0xffffffffu, a2, off);
    }
    if (l == 0) {
        float r = 1.0f / fmaxf((float)cnt, 1.0f);
        float2 w = g_w12[n];
        g_s[n] = make_float2(a1 * r + w.x + g_c[0],
                             a2 * r + w.y + g_c[1]);
    }
}

// -------- pair head: sigmoid(s1[i] + s2[j] + blin) --------
__global__ void k_pairs(const int* __restrict__ mask,
                        const float* __restrict__ blin,
                        float* __restrict__ out, int P)
{
    int p = blockIdx.x * blockDim.x + threadIdx.x;
    if (p >= P) return;
    int i = mask[2 * p], j = mask[2 * p + 1];
    float z = g_s[i].x + g_s[j].y + blin[0];
    out[p] = 1.0f / (1.0f + expf(-z));
}

// ---------------- launch ----------------
extern "C" void kernel_launch(void* const* d_in, const int* in_sizes, int n_in,
                              void* d_out, int out_size)
{
    const float* x    = (const float*)d_in[0];
    const int*   ei   = (const int*)d_in[1];
    const int*   mask = (const int*)d_in[2];
    const float* W1l  = (const float*)d_in[3];
    const float* b1l  = (const float*)d_in[4];
    const float* W1r  = (const float*)d_in[5];
    const float* W2l  = (const float*)d_in[6];
    const float* b2l  = (const float*)d_in[7];
    const float* W2r  = (const float*)d_in[8];
    const float* Wlin = (const float*)d_in[9];
    const float* blin = (const float*)d_in[10];
    float* out = (float*)d_out;

    int E = in_sizes[1] / 2;
    int P = in_sizes[2] / 2;
    const int* src = ei;
    const int* dst = ei + E;

    const int SMEM = (2 * 64 * SA_STRIDE + 2 * 256 * SB_STRIDE) * (int)sizeof(__nv_bfloat16)
                   + 4 * 64 * (int)sizeof(float4);   // 112,640 B
    cudaFuncSetAttribute((const void*)k_l1,
                         cudaFuncAttributeMaxDynamicSharedMemorySize, SMEM);

    k_zero<<<(NODES + 255) / 256, 256>>>();
    k_hist<<<(E + 255) / 256, 256>>>(dst, E);
    k_scan<<<1, 1024>>>();
    k_fill<<<(E + 255) / 256, 256>>>(src, dst, E);
    k_prep<<<1, 256>>>(W2l, W2r, Wlin, b2l);
    k_prepw<<<256, 256>>>(W1l, W1r);
    k_agg1<<<(NODES + 7) / 8, 256>>>(x);
    k_l1<<<(NODES + 63) / 64, 256, SMEM>>>(x, b1l);
    k_fin<<<(NODES * 4 + 255) / 256, 256>>>();
    k_pairs<<<(P + 255) / 256, 256>>>(mask, blin, out, P);
}

// round 7
// speedup vs baseline: 1.1245x; 1.1245x over previous
#include <cuda_runtime.h>
#include <stdint.h>
#include <math.h>

#define NODES 50000
#define EDGES 600000
#define DIN 128
#define DHID 256

typedef unsigned long long u64;

// ---------------- device scratch (static, no allocation) ----------------
__device__ int   g_cnt[NODES];
__device__ int   g_off[NODES];
__device__ int   g_cur[NODES];
__device__ int   g_csrc[EDGES];
__device__ __align__(16) float g_agg1[NODES * DIN];
__device__ float2 g_t12[NODES];
__device__ float2 g_w12[NODES];
__device__ float4 g_P[DHID];
__device__ float  g_c[2];
__device__ float2 g_s[NODES];

// ---------------- f32x2 packed helpers ----------------
__device__ __forceinline__ u64 pack2(float a, float b) {
    u64 r; asm("mov.b64 %0, {%1,%2};" : "=l"(r) : "f"(a), "f"(b)); return r;
}
__device__ __forceinline__ void fma2(u64& d, u64 a, u64 b) {
    asm("fma.rn.f32x2 %0, %1, %2, %0;" : "+l"(d) : "l"(a), "l"(b));
}
__device__ __forceinline__ void unpack2(u64 v, float& a, float& b) {
    asm("mov.b64 {%0,%1}, %2;" : "=f"(a), "=f"(b) : "l"(v));
}

// ---------------- zero the histogram ----------------
__global__ void k_zero() {
    int i = blockIdx.x * blockDim.x + threadIdx.x;
    if (i < NODES) g_cnt[i] = 0;
}

// ---------------- histogram of dst ----------------
__global__ void k_hist(const int* __restrict__ dst, int E) {
    int e = blockIdx.x * blockDim.x + threadIdx.x;
    if (e < E) atomicAdd(&g_cnt[dst[e]], 1);
}

// ---------------- single-block exclusive scan over 50K counts ----------------
__global__ void __launch_bounds__(1024) k_scan() {
    __shared__ int part[1024];
    const int t = threadIdx.x;
    const int per = (NODES + 1023) / 1024;
    const int base = t * per;

    int sum = 0;
    for (int i = 0; i < per; i++) {
        int n = base + i;
        if (n < NODES) sum += g_cnt[n];
    }
    part[t] = sum;
    __syncthreads();
    for (int off = 1; off < 1024; off <<= 1) {
        int u = (t >= off) ? part[t - off] : 0;
        __syncthreads();
        part[t] += u;
        __syncthreads();
    }
    int run = part[t] - sum;
    for (int i = 0; i < per; i++) {
        int n = base + i;
        if (n < NODES) {
            g_off[n] = run;
            g_cur[n] = run;
            run += g_cnt[n];
        }
    }
}

// ---------------- CSR fill ----------------
__global__ void k_fill(const int* __restrict__ src,
                       const int* __restrict__ dst, int E) {
    int e = blockIdx.x * blockDim.x + threadIdx.x;
    if (e >= E) return;
    int d = dst[e];
    int pos = atomicAdd(&g_cur[d], 1);
    g_csrc[pos] = src[e];
}

// ---------------- layer-1 mean aggregate: warp per node, MLP=4 ----------
__global__ void __launch_bounds__(256) k_agg1(const float* __restrict__ x) {
    int n = blockIdx.x * 8 + (threadIdx.x >> 5);
    if (n >= NODES) return;
    int lane = threadIdx.x & 31;
    int start = g_off[n], cnt = g_cnt[n];

    float4 acc = make_float4(0.f, 0.f, 0.f, 0.f);
    int j = 0;
    for (; j + 4 <= cnt; j += 4) {
        int s0 = g_csrc[start + j];
        int s1 = g_csrc[start + j + 1];
        int s2 = g_csrc[start + j + 2];
        int s3 = g_csrc[start + j + 3];
        float4 v0 = ((const float4*)(x + (size_t)s0 * DIN))[lane];
        float4 v1 = ((const float4*)(x + (size_t)s1 * DIN))[lane];
        float4 v2 = ((const float4*)(x + (size_t)s2 * DIN))[lane];
        float4 v3 = ((const float4*)(x + (size_t)s3 * DIN))[lane];
        acc.x += (v0.x + v1.x) + (v2.x + v3.x);
        acc.y += (v0.y + v1.y) + (v2.y + v3.y);
        acc.z += (v0.z + v1.z) + (v2.z + v3.z);
        acc.w += (v0.w + v1.w) + (v2.w + v3.w);
    }
    for (; j < cnt; j++) {
        int s0 = g_csrc[start + j];
        float4 v0 = ((const float4*)(x + (size_t)s0 * DIN))[lane];
        acc.x += v0.x; acc.y += v0.y; acc.z += v0.z; acc.w += v0.w;
    }
    float r = 1.0f / fmaxf((float)cnt, 1.0f);
    acc.x *= r; acc.y *= r; acc.z *= r; acc.w *= r;
    ((float4*)(g_agg1 + (size_t)n * DIN))[lane] = acc;
}

// -------- fold layer 2 + link head into 4 projection vectors --------
__global__ void k_prep(const float* __restrict__ W2l, const float* __restrict__ W2r,
                       const float* __restrict__ Wlin, const float* __restrict__ b2l)
{
    int j = threadIdx.x;
    float u1 = 0.f, u2 = 0.f, v1 = 0.f, v2 = 0.f;
    for (int k = 0; k < DIN; k++) {
        float wa = Wlin[k], wb = Wlin[DIN + k];
        float l = W2l[j * DIN + k], r = W2r[j * DIN + k];
        u1 = fmaf(l, wa, u1); u2 = fmaf(l, wb, u2);
        v1 = fmaf(r, wa, v1); v2 = fmaf(r, wb, v2);
    }
    g_P[j] = make_float4(u1, u2, v1, v2);
    if (j == 0) {
        float c1 = 0.f, c2 = 0.f;
        for (int k = 0; k < DIN; k++) {
            c1 = fmaf(b2l[k], Wlin[k], c1);
            c2 = fmaf(b2l[k], Wlin[DIN + k], c2);
        }
        g_c[0] = c1; g_c[1] = c2;
    }
}

// -------- fused layer-1 GEMM (f32x2 packed FMA) + relu + projection --------
// z[n, 0:256] = [agg1[n], x[n]] @ [W1l ; W1r] + b1l ; h = relu(z)
// outputs t12[n] = (h.u1, h.u2), w12[n] = (h.v1, h.v2)
__global__ void __launch_bounds__(256) k_l1(
    const float* __restrict__ x,
    const float* __restrict__ W1l, const float* __restrict__ W1r,
    const float* __restrict__ b1l)
{
    extern __shared__ float sm[];
    float* sx = sm;             // 64 x 256 input tile
    float* sw = sm + 64 * 256;  // 32 x 256 weight K-chunk

    const int tid = threadIdx.x;
    const int node0 = blockIdx.x * 64;

    // stage input tile: cols 0..127 = agg1 (pre-normalized), cols 128..255 = x
    for (int i = tid; i < 64 * 64; i += 256) {
        int n = i >> 6, q = i & 63;
        int gn = node0 + n;
        float4 v = make_float4(0.f, 0.f, 0.f, 0.f);
        if (gn < NODES) {
            if (q < 32) v = ((const float4*)(g_agg1 + (size_t)gn * DIN))[q];
            else        v = ((const float4*)(x      + (size_t)gn * DIN))[q - 32];
        }
        ((float4*)(sx + n * 256))[q] = v;
    }

    const int warp = tid >> 5, lane = tid & 31;
    // acc[nn][p]: node nn (of 8), p = packed col-pair
    //   p 0,1 -> cols lane*4..+3 (A half), p 2,3 -> cols 128+lane*4..+3 (B half)
    u64 acc[8][4];
#pragma unroll
    for (int a = 0; a < 8; a++)
#pragma unroll
        for (int b = 0; b < 4; b++) acc[a][b] = 0ull;

    for (int kc = 0; kc < 256; kc += 32) {
        __syncthreads();
        for (int i = tid; i < 32 * 64; i += 256) {
            int kk = i >> 6, q = i & 63;
            int k = kc + kk;
            const float4* Wrow = (k < 128)
                ? (const float4*)(W1l + (size_t)k * 256)
                : (const float4*)(W1r + (size_t)(k - 128) * 256);
            ((float4*)(sw + kk * 256))[q] = Wrow[q];
        }
        __syncthreads();
#pragma unroll
        for (int kk = 0; kk < 32; kk += 4) {
            float4 xv[8];
#pragma unroll
            for (int nn = 0; nn < 8; nn++)
                xv[nn] = *((const float4*)(sx + (warp * 8 + nn) * 256 + kc + kk));
#pragma unroll
            for (int dk = 0; dk < 4; dk++) {
                ulonglong2 waP = *((const ulonglong2*)(sw + (kk + dk) * 256 + lane * 4));
                ulonglong2 wbP = *((const ulonglong2*)(sw + (kk + dk) * 256 + 128 + lane * 4));
#pragma unroll
                for (int nn = 0; nn < 8; nn++) {
                    float xs = (dk == 0) ? xv[nn].x : (dk == 1) ? xv[nn].y
                             : (dk == 2) ? xv[nn].z : xv[nn].w;
                    u64 xs2 = pack2(xs, xs);
                    fma2(acc[nn][0], xs2, waP.x);
                    fma2(acc[nn][1], xs2, waP.y);
                    fma2(acc[nn][2], xs2, wbP.x);
                    fma2(acc[nn][3], xs2, wbP.y);
                }
            }
        }
    }

    // epilogue: bias + relu + project onto (u1,u2,v1,v2), warp-reduce per node
    const int cA = lane * 4, cB = 128 + lane * 4;
    float4 bA = *((const float4*)(b1l + cA));
    float4 bB = *((const float4*)(b1l + cB));
    float4 PA0 = g_P[cA], PA1 = g_P[cA + 1], PA2 = g_P[cA + 2], PA3 = g_P[cA + 3];
    float4 PB0 = g_P[cB], PB1 = g_P[cB + 1], PB2 = g_P[cB + 2], PB3 = g_P[cB + 3];

#pragma unroll
    for (int nn = 0; nn < 8; nn++) {
        float a0, a1, a2, a3, a4, a5, a6, a7;
        unpack2(acc[nn][0], a0, a1);
        unpack2(acc[nn][1], a2, a3);
        unpack2(acc[nn][2], a4, a5);
        unpack2(acc[nn][3], a6, a7);
        float h0 = fmaxf(a0 + bA.x, 0.f);
        float h1 = fmaxf(a1 + bA.y, 0.f);
        float h2 = fmaxf(a2 + bA.z, 0.f);
        float h3 = fmaxf(a3 + bA.w, 0.f);
        float h4 = fmaxf(a4 + bB.x, 0.f);
        float h5 = fmaxf(a5 + bB.y, 0.f);
        float h6 = fmaxf(a6 + bB.z, 0.f);
        float h7 = fmaxf(a7 + bB.w, 0.f);
        float t1 = h0*PA0.x + h1*PA1.x + h2*PA2.x + h3*PA3.x
                 + h4*PB0.x + h5*PB1.x + h6*PB2.x + h7*PB3.x;
        float t2 = h0*PA0.y + h1*PA1.y + h2*PA2.y + h3*PA3.y
                 + h4*PB0.y + h5*PB1.y + h6*PB2.y + h7*PB3.y;
        float w1 = h0*PA0.z + h1*PA1.z + h2*PA2.z + h3*PA3.z
                 + h4*PB0.z + h5*PB1.z + h6*PB2.z + h7*PB3.z;
        float w2 = h0*PA0.w + h1*PA1.w + h2*PA2.w + h3*PA3.w
                 + h4*PB0.w + h5*PB1.w + h6*PB2.w + h7*PB3.w;
#pragma unroll
        for (int off = 16; off > 0; off >>= 1) {
            t1 += __shfl_xor_sync(0xffffffffu, t1, off);
            t2 += __shfl_xor_sync(0xffffffffu, t2, off);
            w1 += __shfl_xor_sync(0xffffffffu, w1, off);
            w2 += __shfl_xor_sync(0xffffffffu, w2, off);
        }
        if (lane == 0) {
            int gn = node0 + warp * 8 + nn;
            if (gn < NODES) {
                g_t12[gn] = make_float2(t1, t2);
                g_w12[gn] = make_float2(w1, w2);
            }
        }
    }
}

// -------- layer-2 aggregate (gather) + finalize, 4 lanes per node ------
__global__ void k_fin() {
    int g = blockIdx.x * blockDim.x + threadIdx.x;
    int n = g >> 2, l = g & 3;
    if (n >= NODES) return;
    int start = g_off[n], cnt = g_cnt[n];
    float a1 = 0.f, a2 = 0.f;
    for (int j = l; j < cnt; j += 4) {
        float2 t = g_t12[g_csrc[start + j]];
        a1 += t.x; a2 += t.y;
    }
#pragma unroll
    for (int off = 1; off <= 2; off <<= 1) {
        a1 += __shfl_xor_sync(0xffffffffu, a1, off);
        a2 += __shfl_xor_sync(0xffffffffu, a2, off);
    }
    if (l == 0) {
        float r = 1.0f / fmaxf((float)cnt, 1.0f);
        float2 w = g_w12[n];
        g_s[n] = make_float2(a1 * r + w.x + g_c[0],
                             a2 * r + w.y + g_c[1]);
    }
}

// -------- pair head: sigmoid(s1[i] + s2[j] + blin) --------
__global__ void k_pairs(const int* __restrict__ mask,
                        const float* __restrict__ blin,
                        float* __restrict__ out, int P)
{
    int p = blockIdx.x * blockDim.x + threadIdx.x;
    if (p >= P) return;
    int2 m = ((const int2*)mask)[p];
    float z = g_s[m.x].x + g_s[m.y].y + blin[0];
    out[p] = 1.0f / (1.0f + expf(-z));
}

// ---------------- launch ----------------
extern "C" void kernel_launch(void* const* d_in, const int* in_sizes, int n_in,
                              void* d_out, int out_size)
{
    const float* x    = (const float*)d_in[0];
    const int*   ei   = (const int*)d_in[1];
    const int*   mask = (const int*)d_in[2];
    const float* W1l  = (const float*)d_in[3];
    const float* b1l  = (const float*)d_in[4];
    const float* W1r  = (const float*)d_in[5];
    const float* W2l  = (const float*)d_in[6];
    const float* b2l  = (const float*)d_in[7];
    const float* W2r  = (const float*)d_in[8];
    const float* Wlin = (const float*)d_in[9];
    const float* blin = (const float*)d_in[10];
    float* out = (float*)d_out;

    int E = in_sizes[1] / 2;
    int P = in_sizes[2] / 2;
    const int* src = ei;
    const int* dst = ei + E;

    const int SMEM = (64 * 256 + 32 * 256) * sizeof(float);  // 96 KB
    cudaFuncSetAttribute((const void*)k_l1,
                         cudaFuncAttributeMaxDynamicSharedMemorySize, SMEM);

    k_zero<<<(NODES + 255) / 256, 256>>>();
    k_hist<<<(E + 255) / 256, 256>>>(dst, E);
    k_scan<<<1, 1024>>>();
    k_fill<<<(E + 255) / 256, 256>>>(src, dst, E);
    k_prep<<<1, 256>>>(W2l, W2r, Wlin, b2l);
    k_agg1<<<(NODES + 7) / 8, 256>>>(x);
    k_l1<<<(NODES + 63) / 64, 256, SMEM>>>(x, W1l, W1r, b1l);
    k_fin<<<(NODES * 4 + 255) / 256, 256>>>();
    k_pairs<<<(P + 255) / 256, 256>>>(mask, blin, out, P);
}

// round 9
// speedup vs baseline: 1.2015x; 1.0685x over previous
#include <cuda_runtime.h>
#include <stdint.h>
#include <math.h>

#define NODES 50000
#define EDGES 600000
#define DIN 128
#define DHID 256

// ---------------- device scratch (static, no allocation) ----------------
__device__ int   g_cnt[NODES];
__device__ int   g_off[NODES];
__device__ int   g_cur[NODES];
__device__ int   g_csrc[EDGES];
__device__ __align__(16) float g_agg1[NODES * DIN];
__device__ float2 g_t12[NODES];
__device__ float2 g_w12[NODES];
__device__ float4 g_P[DHID];
__device__ float  g_c[2];
__device__ float2 g_s[NODES];

// ------- zero histogram + fold layer2/link-head into projections -------
// blocks 0..195: zero g_cnt. block 196: compute g_P, g_c.
__global__ void k_zero_prep(const float* __restrict__ W2l,
                            const float* __restrict__ W2r,
                            const float* __restrict__ Wlin,
                            const float* __restrict__ b2l)
{
    if (blockIdx.x < 196) {
        int i = blockIdx.x * 256 + threadIdx.x;
        if (i < NODES) g_cnt[i] = 0;
        return;
    }
    int j = threadIdx.x;   // 0..255 hidden index
    float u1 = 0.f, u2 = 0.f, v1 = 0.f, v2 = 0.f;
    for (int k = 0; k < DIN; k++) {
        float wa = Wlin[k], wb = Wlin[DIN + k];
        float l = W2l[j * DIN + k], r = W2r[j * DIN + k];
        u1 = fmaf(l, wa, u1); u2 = fmaf(l, wb, u2);
        v1 = fmaf(r, wa, v1); v2 = fmaf(r, wb, v2);
    }
    g_P[j] = make_float4(u1, u2, v1, v2);
    if (j == 0) {
        float c1 = 0.f, c2 = 0.f;
        for (int k = 0; k < DIN; k++) {
            c1 = fmaf(b2l[k], Wlin[k], c1);
            c2 = fmaf(b2l[k], Wlin[DIN + k], c2);
        }
        g_c[0] = c1; g_c[1] = c2;
    }
}

// ---------------- histogram of dst: 2 edges per thread ----------------
__global__ void k_hist(const int* __restrict__ dst, int E) {
    int e = (blockIdx.x * blockDim.x + threadIdx.x) * 2;
    if (e + 1 < E) {
        int2 d = *(const int2*)(dst + e);
        atomicAdd(&g_cnt[d.x], 1);
        atomicAdd(&g_cnt[d.y], 1);
    } else if (e < E) {
        atomicAdd(&g_cnt[dst[e]], 1);
    }
}

// ---------------- single-block exclusive scan over 50K counts ----------------
__global__ void __launch_bounds__(1024) k_scan() {
    __shared__ int part[1024];
    const int t = threadIdx.x;
    const int per = (NODES + 1023) / 1024;
    const int base = t * per;
    int sum = 0;
    for (int i = 0; i < per; i++) {
        int n = base + i;
        if (n < NODES) sum += g_cnt[n];
    }
    part[t] = sum;
    __syncthreads();
    for (int off = 1; off < 1024; off <<= 1) {
        int u = (t >= off) ? part[t - off] : 0;
        __syncthreads();
        part[t] += u;
        __syncthreads();
    }
    int run = part[t] - sum;
    for (int i = 0; i < per; i++) {
        int n = base + i;
        if (n < NODES) {
            g_off[n] = run;
            g_cur[n] = run;
            run += g_cnt[n];
        }
    }
}

// ---------------- CSR fill: 2 edges per thread ----------------
__global__ void k_fill(const int* __restrict__ src,
                       const int* __restrict__ dst, int E) {
    int e = (blockIdx.x * blockDim.x + threadIdx.x) * 2;
    if (e + 1 < E) {
        int2 s = *(const int2*)(src + e);
        int2 d = *(const int2*)(dst + e);
        int p0 = atomicAdd(&g_cur[d.x], 1);
        g_csrc[p0] = s.x;
        int p1 = atomicAdd(&g_cur[d.y], 1);
        g_csrc[p1] = s.y;
    } else if (e < E) {
        int pos = atomicAdd(&g_cur[dst[e]], 1);
        g_csrc[pos] = src[e];
    }
}

// ---------------- layer-1 mean aggregate: warp per node, MLP=4 ----------
__global__ void __launch_bounds__(256) k_agg1(const float* __restrict__ x) {
    int n = blockIdx.x * 8 + (threadIdx.x >> 5);
    if (n >= NODES) return;
    int lane = threadIdx.x & 31;
    int start = g_off[n], cnt = g_cnt[n];
    float4 acc = make_float4(0.f, 0.f, 0.f, 0.f);
    int j = 0;
    for (; j + 4 <= cnt; j += 4) {
        int s0 = g_csrc[start + j];
        int s1 = g_csrc[start + j + 1];
        int s2 = g_csrc[start + j + 2];
        int s3 = g_csrc[start + j + 3];
        float4 v0 = ((const float4*)(x + (size_t)s0 * DIN))[lane];
        float4 v1 = ((const float4*)(x + (size_t)s1 * DIN))[lane];
        float4 v2 = ((const float4*)(x + (size_t)s2 * DIN))[lane];
        float4 v3 = ((const float4*)(x + (size_t)s3 * DIN))[lane];
        acc.x += (v0.x + v1.x) + (v2.x + v3.x);
        acc.y += (v0.y + v1.y) + (v2.y + v3.y);
        acc.z += (v0.z + v1.z) + (v2.z + v3.z);
        acc.w += (v0.w + v1.w) + (v2.w + v3.w);
    }
    for (; j < cnt; j++) {
        int s0 = g_csrc[start + j];
        float4 v0 = ((const float4*)(x + (size_t)s0 * DIN))[lane];
        acc.x += v0.x; acc.y += v0.y; acc.z += v0.z; acc.w += v0.w;
    }
    float r = 1.0f / fmaxf((float)cnt, 1.0f);
    acc.x *= r; acc.y *= r; acc.z *= r; acc.w *= r;
    ((float4*)(g_agg1 + (size_t)n * DIN))[lane] = acc;
}

// -------- fused layer-1 GEMM + relu + 4-vector projection epilogue --------
// (identical to the 330us round-3 kernel)
__global__ void __launch_bounds__(256) k_l1(
    const float* __restrict__ x,
    const float* __restrict__ W1l, const float* __restrict__ W1r,
    const float* __restrict__ b1l)
{
    extern __shared__ float sm[];
    float* sx = sm;             // 64 x 256 input tile
    float* sw = sm + 64 * 256;  // 32 x 256 weight K-chunk

    const int tid = threadIdx.x;
    const int node0 = blockIdx.x * 64;

    for (int i = tid; i < 64 * 64; i += 256) {
        int n = i >> 6, q = i & 63;
        int gn = node0 + n;
        float4 v = make_float4(0.f, 0.f, 0.f, 0.f);
        if (gn < NODES) {
            if (q < 32) v = ((const float4*)(g_agg1 + (size_t)gn * DIN))[q];
            else        v = ((const float4*)(x      + (size_t)gn * DIN))[q - 32];
        }
        ((float4*)(sx + n * 256))[q] = v;
    }

    const int warp = tid >> 5, lane = tid & 31;
    float acc[8][8];
#pragma unroll
    for (int a = 0; a < 8; a++)
#pragma unroll
        for (int b = 0; b < 8; b++) acc[a][b] = 0.f;

    for (int kc = 0; kc < 256; kc += 32) {
        __syncthreads();
        for (int i = tid; i < 32 * 64; i += 256) {
            int kk = i >> 6, q = i & 63;
            int k = kc + kk;
            const float4* Wrow = (k < 128)
                ? (const float4*)(W1l + (size_t)k * 256)
                : (const float4*)(W1r + (size_t)(k - 128) * 256);
            ((float4*)(sw + kk * 256))[q] = Wrow[q];
        }
        __syncthreads();
#pragma unroll
        for (int kk = 0; kk < 32; kk += 4) {
            float4 xv[8];
#pragma unroll
            for (int nn = 0; nn < 8; nn++)
                xv[nn] = *((const float4*)(sx + (warp * 8 + nn) * 256 + kc + kk));
#pragma unroll
            for (int dk = 0; dk < 4; dk++) {
                float4 wa = *((const float4*)(sw + (kk + dk) * 256 + lane * 4));
                float4 wb = *((const float4*)(sw + (kk + dk) * 256 + 128 + lane * 4));
#pragma unroll
                for (int nn = 0; nn < 8; nn++) {
                    float xs = (dk == 0) ? xv[nn].x : (dk == 1) ? xv[nn].y
                             : (dk == 2) ? xv[nn].z : xv[nn].w;
                    acc[nn][0] = fmaf(xs, wa.x, acc[nn][0]);
                    acc[nn][1] = fmaf(xs, wa.y, acc[nn][1]);
                    acc[nn][2] = fmaf(xs, wa.z, acc[nn][2]);
                    acc[nn][3] = fmaf(xs, wa.w, acc[nn][3]);
                    acc[nn][4] = fmaf(xs, wb.x, acc[nn][4]);
                    acc[nn][5] = fmaf(xs, wb.y, acc[nn][5]);
                    acc[nn][6] = fmaf(xs, wb.z, acc[nn][6]);
                    acc[nn][7] = fmaf(xs, wb.w, acc[nn][7]);
                }
            }
        }
    }

    const int cA = lane * 4, cB = 128 + lane * 4;
    float4 bA = *((const float4*)(b1l + cA));
    float4 bB = *((const float4*)(b1l + cB));
    float4 PA0 = g_P[cA], PA1 = g_P[cA + 1], PA2 = g_P[cA + 2], PA3 = g_P[cA + 3];
    float4 PB0 = g_P[cB], PB1 = g_P[cB + 1], PB2 = g_P[cB + 2], PB3 = g_P[cB + 3];

#pragma unroll
    for (int nn = 0; nn < 8; nn++) {
        float h0 = fmaxf(acc[nn][0] + bA.x, 0.f);
        float h1 = fmaxf(acc[nn][1] + bA.y, 0.f);
        float h2 = fmaxf(acc[nn][2] + bA.z, 0.f);
        float h3 = fmaxf(acc[nn][3] + bA.w, 0.f);
        float h4 = fmaxf(acc[nn][4] + bB.x, 0.f);
        float h5 = fmaxf(acc[nn][5] + bB.y, 0.f);
        float h6 = fmaxf(acc[nn][6] + bB.z, 0.f);
        float h7 = fmaxf(acc[nn][7] + bB.w, 0.f);
        float t1 = h0*PA0.x + h1*PA1.x + h2*PA2.x + h3*PA3.x
                 + h4*PB0.x + h5*PB1.x + h6*PB2.x + h7*PB3.x;
        float t2 = h0*PA0.y + h1*PA1.y + h2*PA2.y + h3*PA3.y
                 + h4*PB0.y + h5*PB1.y + h6*PB2.y + h7*PB3.y;
        float w1 = h0*PA0.z + h1*PA1.z + h2*PA2.z + h3*PA3.z
                 + h4*PB0.z + h5*PB1.z + h6*PB2.z + h7*PB3.z;
        float w2 = h0*PA0.w + h1*PA1.w + h2*PA2.w + h3*PA3.w
                 + h4*PB0.w + h5*PB1.w + h6*PB2.w + h7*PB3.w;
#pragma unroll
        for (int off = 16; off > 0; off >>= 1) {
            t1 += __shfl_xor_sync(0xffffffffu, t1, off);
            t2 += __shfl_xor_sync(0xffffffffu, t2, off);
            w1 += __shfl_xor_sync(0xffffffffu, w1, off);
            w2 += __shfl_xor_sync(0xffffffffu, w2, off);
        }
        if (lane == 0) {
            int gn = node0 + warp * 8 + nn;
            if (gn < NODES) {
                g_t12[gn] = make_float2(t1, t2);
                g_w12[gn] = make_float2(w1, w2);
            }
        }
    }
}

// -------- layer-2 aggregate (gather) + finalize, 4 lanes per node ------
__global__ void k_fin() {
    int g = blockIdx.x * blockDim.x + threadIdx.x;
    int n = g >> 2, l = g & 3;
    if (n >= NODES) return;
    int start = g_off[n], cnt = g_cnt[n];
    float a1 = 0.f, a2 = 0.f;
    for (int j = l; j < cnt; j += 4) {
        float2 t = g_t12[g_csrc[start + j]];
        a1 += t.x; a2 += t.y;
    }
#pragma unroll
    for (int off = 1; off <= 2; off <<= 1) {
        a1 += __shfl_xor_sync(0xffffffffu, a1, off);
        a2 += __shfl_xor_sync(0xffffffffu, a2, off);
    }
    if (l == 0) {
        float r = 1.0f / fmaxf((float)cnt, 1.0f);
        float2 w = g_w12[n];
        g_s[n] = make_float2(a1 * r + w.x + g_c[0],
                             a2 * r + w.y + g_c[1]);
    }
}

// -------- pair head: sigmoid(s1[i] + s2[j] + blin) --------
__global__ void k_pairs(const int* __restrict__ mask,
                        const float* __restrict__ blin,
                        float* __restrict__ out, int P)
{
    int p = blockIdx.x * blockDim.x + threadIdx.x;
    if (p >= P) return;
    int2 m = ((const int2*)mask)[p];
    float z = g_s[m.x].x + g_s[m.y].y + blin[0];
    out[p] = 1.0f / (1.0f + expf(-z));
}

// ---------------- launch ----------------
extern "C" void kernel_launch(void* const* d_in, const int* in_sizes, int n_in,
                              void* d_out, int out_size)
{
    const float* x    = (const float*)d_in[0];
    const int*   ei   = (const int*)d_in[1];
    const int*   mask = (const int*)d_in[2];
    const float* W1l  = (const float*)d_in[3];
    const float* b1l  = (const float*)d_in[4];
    const float* W1r  = (const float*)d_in[5];
    const float* W2l  = (const float*)d_in[6];
    const float* b2l  = (const float*)d_in[7];
    const float* W2r  = (const float*)d_in[8];
    const float* Wlin = (const float*)d_in[9];
    const float* blin = (const float*)d_in[10];
    float* out = (float*)d_out;

    int E = in_sizes[1] / 2;
    int P = in_sizes[2] / 2;
    const int* src = ei;
    const int* dst = ei + E;

    const int SMEM = (64 * 256 + 32 * 256) * sizeof(float);  // 96 KB
    cudaFuncSetAttribute((const void*)k_l1,
                         cudaFuncAttributeMaxDynamicSharedMemorySize, SMEM);

    k_zero_prep<<<197, 256>>>(W2l, W2r, Wlin, b2l);
    k_hist<<<(E / 2 + 255) / 256, 256>>>(dst, E);
    k_scan<<<1, 1024>>>();
    k_fill<<<(E / 2 + 255) / 256, 256>>>(src, dst, E);
    k_agg1<<<(NODES + 7) / 8, 256>>>(x);
    k_l1<<<(NODES + 63) / 64, 256, SMEM>>>(x, W1l, W1r, b1l);
    k_fin<<<(NODES * 4 + 255) / 256, 256>>>();
    k_pairs<<<(P + 255) / 256, 256>>>(mask, blin, out, P);
}